// round 1
// baseline (speedup 1.0000x reference)
#include <cuda_runtime.h>

// DerivativeDILATEloss: soft-DTW(gamma=0.01) over D[i,j] = (dy[i]-dx[j])^2,
// dx/dy = first differences of input/target. B=64, N=512 -> n=511. Output:
// scalar mean over batch (ALPHA=1).
//
// Baseline: one CTA per batch, anti-diagonal wavefront, 3 rotating diagonals
// in shared memory, one __syncthreads per diagonal (2n-1 = 1021 steps).

#define SEQ_N   511          // n = N-1
#define NTHR    512          // n+1 threads (diagonal length)
#define NBATCH  64
#define INF_F   1.0e9f
#define GAMMA_F 0.01f
#define INV_G   100.0f

__device__ float g_partial[NBATCH];

__global__ __launch_bounds__(NTHR, 1)
void sdtw_kernel(const float* __restrict__ input,
                 const float* __restrict__ target)
{
    __shared__ float sdx[SEQ_N];
    __shared__ float sdy[SEQ_N];
    __shared__ float rbuf[3][NTHR];

    const int b   = blockIdx.x;
    const int tid = threadIdx.x;

    const float* in_b = input  + b * (SEQ_N + 1);
    const float* tg_b = target + b * (SEQ_N + 1);

    if (tid < SEQ_N) {
        sdx[tid] = in_b[tid + 1] - in_b[tid];
        sdy[tid] = tg_b[tid + 1] - tg_b[tid];
    }

    // diag d=0: R[0,0]=0, rest INF ; diag d=1: all INF
    rbuf[0][tid] = (tid == 0) ? 0.0f : INF_F;
    rbuf[1][tid] = INF_F;
    __syncthreads();

    float* r2 = rbuf[0];   // diag d-2
    float* r1 = rbuf[1];   // diag d-1
    float* rn = rbuf[2];   // diag d (being written)

    const int ii  = tid;                       // row index on diagonal
    const int im1 = (ii >= 1) ? ii - 1 : 0;    // clamped (masked below)

    #pragma unroll 1
    for (int d = 2; d <= 2 * SEQ_N; ++d) {
        const int jj  = d - ii;
        const int jm1c = min(max(jj - 1, 0), SEQ_N - 1);
        const bool valid = (ii >= 1) && (jj >= 1) && (jj <= SEQ_N);

        // softmin_gamma(r2[ii-1], r1[ii-1], r1[ii]) -- stable form
        const float a = r2[im1];
        const float e = r1[im1];
        const float c = r1[ii];
        const float m = fminf(a, fminf(e, c));
        const float s = __expf((m - a) * INV_G)
                      + __expf((m - e) * INV_G)
                      + __expf((m - c) * INV_G);
        const float smin = m - GAMMA_F * __logf(s);

        const float dv  = sdy[im1] - sdx[jm1c];
        const float val = valid ? (dv * dv + smin) : INF_F;

        rn[tid] = val;
        __syncthreads();

        float* t = r2; r2 = r1; r1 = rn; rn = t;  // rotate
    }

    // last written diagonal is now r1; result at index n
    if (tid == SEQ_N) g_partial[b] = r1[SEQ_N];
}

__global__ void reduce_kernel(float* __restrict__ out)
{
    // single thread, fixed order -> deterministic
    float s = 0.0f;
    #pragma unroll
    for (int i = 0; i < NBATCH; ++i) s += g_partial[i];
    out[0] = s * (1.0f / (float)NBATCH);   // ALPHA = 1
}

extern "C" void kernel_launch(void* const* d_in, const int* in_sizes, int n_in,
                              void* d_out, int out_size)
{
    const float* input  = (const float*)d_in[0];
    const float* target = (const float*)d_in[1];
    float* out = (float*)d_out;

    sdtw_kernel<<<NBATCH, NTHR>>>(input, target);
    reduce_kernel<<<1, 1>>>(out);
}